// round 14
// baseline (speedup 1.0000x reference)
#include <cuda_runtime.h>
#include <math_constants.h>
#include <stdint.h>

#define NTOT   18432
#define TPB    512
#define STRIP  512
#define NSTRIP 12
#define NUNITS 144              /* 132 offdiag halves + 12 diag */
#define GRID   147              /* 2 quantile + 1 std + 144 pairwise */
#define NWARPS 16
#define GMAX   1024
#define SELMAX 48
#define NV4    4608             /* NTOT / 4 */
#define SMEM_BYTES 16512

static const double NPAIRS_D = 18871296.0;
static const double RAND_STD = 1.75;
static const double IQR_RAND = 2.45;

__device__ double   g_pair_partial[NUNITS];
__device__ double   g_sum_d, g_sumsq_d;
__device__ float    g_qv[4];

typedef unsigned long long u64;
__device__ __forceinline__ float sqrt_approx(float x) {
    float r; asm("sqrt.approx.f32 %0, %1;" : "=f"(r) : "f"(x)); return r;
}
__device__ __forceinline__ u64 addx2(u64 a, u64 b) {
    u64 r; asm("add.rn.f32x2 %0, %1, %2;" : "=l"(r) : "l"(a), "l"(b)); return r;
}
__device__ __forceinline__ u64 fmax2(u64 a, u64 b, u64 c) {
    u64 r; asm("fma.rn.f32x2 %0, %1, %2, %3;" : "=l"(r) : "l"(a), "l"(b), "l"(c)); return r;
}
__device__ __forceinline__ u64 pack2(float lo, float hi) {
    u64 r; asm("mov.b64 %0, {%1, %2};" : "=l"(r) : "f"(lo), "f"(hi)); return r;
}
__device__ __forceinline__ void unpack2(u64 v, float& lo, float& hi) {
    asm("mov.b64 {%0, %1}, %2;" : "=f"(lo), "=f"(hi) : "l"(v));
}
__device__ __forceinline__ unsigned fkey(float f) {
    unsigned u = __float_as_uint(f);
    return (u & 0x80000000u) ? ~u : (u | 0x80000000u);
}
__device__ __forceinline__ float funkey(unsigned u) {
    unsigned bits = (u & 0x80000000u) ? (u & 0x7fffffffu) : ~u;
    return __uint_as_float(bits);
}
__device__ __forceinline__ void hit(float s, float& acc) {
    if (s < 0.64f) acc += 0.8f - sqrt_approx(fmaxf(s, 0.0f));
}

/* packed broadcast pair loop: PA[m]={x0,x1,y0,y1}, PZ[m]={z0,z1,r0,r1} */
__device__ __forceinline__ void pair_loop(const float4* __restrict__ PA,
                                          const float4* __restrict__ PZ,
                                          int m0, int cnt,
                                          u64 R2, u64 A2, u64 B2, u64 C2,
                                          float& acc) {
    #pragma unroll 2
    for (int q = 0; q < cnt; q += 2) {
        float4 v0 = PA[m0 + q],     z0 = PZ[m0 + q];
        float4 v1 = PA[m0 + q + 1], z1 = PZ[m0 + q + 1];
        u64 sa = addx2(R2, pack2(z0.z, z0.w));
        sa = fmax2(pack2(v0.x, v0.y), A2, sa);
        sa = fmax2(pack2(v0.z, v0.w), B2, sa);
        sa = fmax2(pack2(z0.x, z0.y), C2, sa);
        u64 sb = addx2(R2, pack2(z1.z, z1.w));
        sb = fmax2(pack2(v1.x, v1.y), A2, sb);
        sb = fmax2(pack2(v1.z, v1.w), B2, sb);
        sb = fmax2(pack2(z1.x, z1.y), C2, sb);
        float a0, a1, b0, b1;
        unpack2(sa, a0, a1); unpack2(sb, b0, b1);
        float mn = fminf(fminf(a0, a1), fminf(b0, b1));
        if (mn < 0.64f) { hit(a0, acc); hit(a1, acc); hit(b0, acc); hit(b1, acc); }
    }
}

__global__ void __launch_bounds__(TPB)
dp_main_kernel(const float* __restrict__ g) {
    extern __shared__ unsigned char smem_raw[];
    const int bid = blockIdx.x;
    const int t   = threadIdx.x;
    const int w   = t >> 5;
    const int ln  = t & 31;

    __shared__ unsigned s_wcnt[NWARPS], s_wcnt2[NWARPS];
    __shared__ unsigned s_totA, s_totB, s_tot, s_gcnt, s_gcnt2;
    __shared__ float    s_fred[NWARPS];
    __shared__ float    s_q[2];

    if (bid >= 3 && bid < 3 + 132) {
        /* ===== off-diag half: i-strip a (512) x j-window 256 of strip b ===== */
        const int ob = bid - 3;
        const int tile = ob >> 1, h = ob & 1;
        int a = 0, rem = tile;
        while (rem >= NSTRIP - 1 - a) { rem -= NSTRIP - 1 - a; ++a; }
        const int b = a + 1 + rem;

        float4* PA = (float4*)smem_raw;         /* 128 pair-float4s */
        float4* PZ = PA + 128;
        if (t < 256) {
            const int j = b * STRIP + h * 256 + t;
            float xj = g[3 * j + 0], yj = g[3 * j + 1], zj = g[3 * j + 2];
            float rj = fmaf(zj, zj, fmaf(yj, yj, xj * xj));
            const int m = t >> 1, c = t & 1;
            ((float*)&PA[m])[c]     = xj;
            ((float*)&PA[m])[2 + c] = yj;
            ((float*)&PZ[m])[c]     = zj;
            ((float*)&PZ[m])[2 + c] = rj;
        }
        float xi, yi, zi;
        {
            const int i = a * STRIP + t;
            xi = g[3 * i + 0]; yi = g[3 * i + 1]; zi = g[3 * i + 2];
        }
        __syncthreads();

        const float Ri = fmaf(zi, zi, fmaf(yi, yi, xi * xi));
        const u64 R2 = pack2(Ri, Ri);
        const u64 A2 = pack2(-2.0f * xi, -2.0f * xi);
        const u64 B2 = pack2(-2.0f * yi, -2.0f * yi);
        const u64 C2 = pack2(-2.0f * zi, -2.0f * zi);

        float acc = 0.f;
        pair_loop(PA, PZ, 0, 128, R2, A2, B2, C2, acc);

        #pragma unroll
        for (int o = 16; o; o >>= 1)
            acc += __shfl_down_sync(0xffffffffu, acc, o);
        if (ln == 0) s_fred[w] = acc;
        __syncthreads();
        if (t == 0) {
            float r = 0.f;
            #pragma unroll
            for (int i2 = 0; i2 < NWARPS; ++i2) r += s_fred[i2];
            g_pair_partial[ob] = (double)r;
        }

    } else if (bid >= 3 + 132) {
        /* ===== diag strip: recursive half-split squares + shfl tri(16) ===== */
        const int db = bid - (3 + 132);           /* 0..11 */
        float4* F4 = (float4*)smem_raw;           /* 512 atoms */
        float4* PA = F4 + 512;                    /* 256 pair-float4s */
        float4* PZ = PA + 256;
        {
            const int j = db * STRIP + t;
            float xj = g[3 * j + 0], yj = g[3 * j + 1], zj = g[3 * j + 2];
            float rj = fmaf(zj, zj, fmaf(yj, yj, xj * xj));
            F4[t] = make_float4(xj, yj, zj, rj);
            const int m = t >> 1, c = t & 1;
            ((float*)&PA[m])[c]     = xj;
            ((float*)&PA[m])[2 + c] = yj;
            ((float*)&PZ[m])[c]     = zj;
            ((float*)&PZ[m])[2 + c] = rj;
        }
        __syncthreads();

        float acc = 0.f;
        #pragma unroll
        for (int L = 0; L < 5; ++L) {
            const int halfsz = 256 >> L;
            const int sqid = t >> (9 - L);
            const int r    = t & ((512 >> L) - 1);
            const int il   = sqid * (512 >> L) + (r & (halfsz - 1));
            const int jh   = r >> (8 - L);
            const int j0   = sqid * (512 >> L) + halfsz + jh * (halfsz >> 1);
            float4 mi = F4[il];
            const u64 R2 = pack2(mi.w, mi.w);
            const u64 A2 = pack2(-2.0f * mi.x, -2.0f * mi.x);
            const u64 B2 = pack2(-2.0f * mi.y, -2.0f * mi.y);
            const u64 C2 = pack2(-2.0f * mi.z, -2.0f * mi.z);
            pair_loop(PA, PZ, j0 >> 1, 64 >> L, R2, A2, B2, C2, acc);
        }
        /* tri(16) groups via shuffle */
        {
            float4 me = F4[t];
            const float mx = -2.0f * me.x, my = -2.0f * me.y, mz = -2.0f * me.z;
            const int hl = t & 15;
            #pragma unroll
            for (int d = 1; d <= 8; ++d) {
                int src = (hl + d) & 15;
                float xo = __shfl_sync(0xffffffffu, me.x, src, 16);
                float yo = __shfl_sync(0xffffffffu, me.y, src, 16);
                float zo = __shfl_sync(0xffffffffu, me.z, src, 16);
                float ro = __shfl_sync(0xffffffffu, me.w, src, 16);
                if (d < 8 || hl < 8) {
                    float s = fmaf(mz, zo, fmaf(my, yo, fmaf(mx, xo, me.w + ro)));
                    hit(s, acc);
                }
            }
        }

        #pragma unroll
        for (int o = 16; o; o >>= 1)
            acc += __shfl_down_sync(0xffffffffu, acc, o);
        if (ln == 0) s_fred[w] = acc;
        __syncthreads();
        if (t == 0) {
            float r = 0.f;
            #pragma unroll
            for (int i2 = 0; i2 < NWARPS; ++i2) r += s_fred[i2];
            g_pair_partial[132 + db] = (double)r;
        }

    } else if (bid < 2) {
        /* ===== exact quantile pair (ranks k0, k0+1): fused fast bracket ===== */
        const int qb = bid;
        const unsigned k0 = qb ? 13823u : 4607u;
        const float gA = qb ? 0.6245f : -0.7245f;
        const float gB = qb ? 0.7245f : -0.6245f;
        const float4* gv4 = (const float4*)g;
        float* sub  = (float*)smem_raw;
        float* sub2 = sub + GMAX;

        float lo, hi; unsigned cL, cH;
        bool allEq = false;

        if (t == 0) s_gcnt = 0;
        __syncthreads();

        {
            unsigned cA = 0, cB = 0;
            for (int e = t; e < NV4; e += TPB) {
                float4 q = gv4[e];
                float qq[4] = {q.x, q.y, q.z, q.w};
                #pragma unroll
                for (int c4 = 0; c4 < 4; ++c4) {
                    float x = qq[c4];
                    cA += (x < gA) ? 1u : 0u;
                    cB += (x < gB) ? 1u : 0u;
                    if (x >= gA && x < gB) {
                        unsigned p = atomicAdd(&s_gcnt, 1u);
                        if (p < (unsigned)GMAX) sub[p] = x;
                    }
                }
            }
            #pragma unroll
            for (int o = 16; o; o >>= 1) {
                cA += __shfl_down_sync(0xffffffffu, cA, o);
                cB += __shfl_down_sync(0xffffffffu, cB, o);
            }
            if (ln == 0) { s_wcnt[w] = cA; s_wcnt2[w] = cB; }
            __syncthreads();
            if (t == 0) {
                unsigned ta = 0, tb = 0;
                #pragma unroll
                for (int i2 = 0; i2 < NWARPS; ++i2) { ta += s_wcnt[i2]; tb += s_wcnt2[i2]; }
                s_totA = ta; s_totB = tb;
            }
            __syncthreads();
        }

        const bool fast = (s_totA <= k0) && (k0 < s_totB) &&
                          (s_totB - s_totA <= (unsigned)GMAX);
        if (fast) {
            lo = gA; hi = gB; cL = s_totA; cH = s_totB;
        } else {
            lo = -CUDART_INF_F; hi = CUDART_INF_F; cL = 0; cH = NTOT;
            for (int it = 0; it < 48; ++it) {
                if (cH - cL <= (unsigned)GMAX) break;
                const unsigned klo = fkey(lo), khi = fkey(hi);
                if (khi - klo <= 1u) { allEq = true; break; }
                float cand;
                if (it < 8) {
                    double frac = ((double)k0 + 0.5 - (double)cL) / (double)(cH - cL);
                    if (lo == -CUDART_INF_F || hi == CUDART_INF_F)
                        cand = funkey(klo + (khi - klo) / 2u);
                    else
                        cand = (float)((double)lo + frac * ((double)hi - (double)lo));
                } else cand = funkey(klo + (khi - klo) / 2u);
                {
                    unsigned kc = fkey(cand);
                    if (!(kc > klo && kc < khi)) cand = funkey(klo + (khi - klo) / 2u);
                }
                unsigned c = 0;
                for (int e = t; e < NV4; e += TPB) {
                    float4 q = gv4[e];
                    c += (q.x < cand) ? 1u : 0u;
                    c += (q.y < cand) ? 1u : 0u;
                    c += (q.z < cand) ? 1u : 0u;
                    c += (q.w < cand) ? 1u : 0u;
                }
                #pragma unroll
                for (int o = 16; o; o >>= 1) c += __shfl_down_sync(0xffffffffu, c, o);
                if (ln == 0) s_wcnt[w] = c;
                __syncthreads();
                if (t == 0) {
                    unsigned totc = 0;
                    #pragma unroll
                    for (int i2 = 0; i2 < NWARPS; ++i2) totc += s_wcnt[i2];
                    s_tot = totc;
                }
                __syncthreads();
                const unsigned ctot = s_tot;
                if (ctot <= k0) { lo = cand; cL = ctot; }
                else            { hi = cand; cH = ctot; }
            }
            if (!allEq) {
                __syncthreads();
                if (t == 0) s_gcnt = 0;
                __syncthreads();
                for (int e = t; e < NV4; e += TPB) {
                    float4 q = gv4[e];
                    float qq[4] = {q.x, q.y, q.z, q.w};
                    #pragma unroll
                    for (int c4 = 0; c4 < 4; ++c4) {
                        float x = qq[c4];
                        if (x >= lo && x < hi) {
                            unsigned p = atomicAdd(&s_gcnt, 1u);
                            if (p < (unsigned)GMAX) sub[p] = x;
                        }
                    }
                }
                __syncthreads();
            }
        }

        if (allEq) {
            if (t == 0) { s_q[0] = lo; s_q[1] = lo; }
            __syncthreads();
        } else {
            __syncthreads();
            const unsigned mm0 = s_gcnt;
            const unsigned cL0 = cL;

            unsigned cLg = cL, cHg = cH;
            float lo2 = lo, hi2 = hi;
            for (int it = 0; it < 64; ++it) {
                if (cHg - cLg <= (unsigned)SELMAX) break;
                const unsigned klo = fkey(lo2), khi = fkey(hi2);
                if (khi - klo <= 1u) break;
                float cand;
                if (it < 10) {
                    double frac = ((double)k0 + 0.5 - (double)cLg) / (double)(cHg - cLg);
                    cand = (float)((double)lo2 + frac * ((double)hi2 - (double)lo2));
                } else cand = funkey(klo + (khi - klo) / 2u);
                {
                    unsigned kc = fkey(cand);
                    if (!(kc > klo && kc < khi)) cand = funkey(klo + (khi - klo) / 2u);
                }
                unsigned c = 0;
                for (unsigned i2 = t; i2 < mm0; i2 += TPB)
                    c += (sub[i2] < cand) ? 1u : 0u;
                #pragma unroll
                for (int o = 16; o; o >>= 1) c += __shfl_down_sync(0xffffffffu, c, o);
                if (ln == 0) s_wcnt[w] = c;
                __syncthreads();
                if (t == 0) {
                    unsigned totc = 0;
                    #pragma unroll
                    for (int i2 = 0; i2 < NWARPS; ++i2) totc += s_wcnt[i2];
                    s_tot = totc;
                }
                __syncthreads();
                const unsigned cg = cL0 + s_tot;
                if (cg <= k0) { lo2 = cand; cLg = cg; }
                else          { hi2 = cand; cHg = cg; }
            }

            if (t == 0) s_gcnt2 = 0;
            __syncthreads();
            for (unsigned i2 = t; i2 < mm0; i2 += TPB) {
                float x = sub[i2];
                if (x >= lo2 && x < hi2) {
                    unsigned p = atomicAdd(&s_gcnt2, 1u);
                    if (p < 64u) sub2[p] = x;
                }
            }
            __syncthreads();
            const unsigned mm2 = s_gcnt2;
            if (mm2 <= 64u) {
                if (t < (int)mm2) {
                    float x = sub2[t];
                    unsigned cl = 0, ce = 0;
                    for (unsigned jj = 0; jj < mm2; ++jj) {
                        float y = sub2[jj];
                        cl += (y < x) ? 1u : 0u;
                        ce += (y == x) ? 1u : 0u;
                    }
                    const unsigned glo = cLg + cl;
                    if (glo <= k0 && k0 < glo + ce)           s_q[0] = x;
                    if (glo <= k0 + 1u && k0 + 1u < glo + ce) s_q[1] = x;
                }
            } else {
                for (unsigned i2 = t; i2 < mm0; i2 += TPB) {
                    float x = sub[i2];
                    if (x >= lo2 && x < hi2) {
                        unsigned cl = 0, ce = 0;
                        for (unsigned jj = 0; jj < mm0; ++jj) {
                            float y = sub[jj];
                            cl += (y < x) ? 1u : 0u;
                            ce += (y == x) ? 1u : 0u;
                        }
                        const unsigned glo = cL0 + cl;
                        if (glo <= k0 && k0 < glo + ce)           s_q[0] = x;
                        if (glo <= k0 + 1u && k0 + 1u < glo + ce) s_q[1] = x;
                    }
                }
            }
            if (k0 + 1u >= cHg) {
                float mn = CUDART_INF_F;
                for (int e = t; e < NV4; e += TPB) {
                    float4 q = gv4[e];
                    if (q.x >= hi2) mn = fminf(mn, q.x);
                    if (q.y >= hi2) mn = fminf(mn, q.y);
                    if (q.z >= hi2) mn = fminf(mn, q.z);
                    if (q.w >= hi2) mn = fminf(mn, q.w);
                }
                #pragma unroll
                for (int o = 16; o; o >>= 1)
                    mn = fminf(mn, __shfl_down_sync(0xffffffffu, mn, o));
                if (ln == 0) s_fred[w] = mn;
                __syncthreads();
                if (t == 0) {
                    float r = s_fred[0];
                    #pragma unroll
                    for (int i2 = 1; i2 < NWARPS; ++i2) r = fminf(r, s_fred[i2]);
                    s_q[1] = r;
                }
            }
            __syncthreads();
        }
        if (t == 0) {
            g_qv[2 * qb + 0] = s_q[0];
            g_qv[2 * qb + 1] = s_q[1];
        }

    } else {
        /* ============ std sums (fp64, deterministic) ============ */
        __shared__ double sds[NWARPS], sdq[NWARPS];
        const float4* gv4 = (const float4*)g;
        double s = 0.0, s2 = 0.0;
        for (int e = t; e < NV4; e += TPB) {
            float4 q = gv4[e];
            double x0 = (double)q.x, x1 = (double)q.y;
            double x2 = (double)q.z, x3 = (double)q.w;
            s  += (x0 + x1) + (x2 + x3);
            s2 += (x0 * x0 + x1 * x1) + (x2 * x2 + x3 * x3);
        }
        #pragma unroll
        for (int o = 16; o; o >>= 1) {
            s  += __shfl_down_sync(0xffffffffu, s,  o);
            s2 += __shfl_down_sync(0xffffffffu, s2, o);
        }
        if (ln == 0) { sds[w] = s; sdq[w] = s2; }
        __syncthreads();
        if (t == 0) {
            double aa = 0.0, bb = 0.0;
            #pragma unroll
            for (int i2 = 0; i2 < NWARPS; ++i2) { aa += sds[i2]; bb += sdq[i2]; }
            g_sum_d = aa; g_sumsq_d = bb;
        }
    }
}

__global__ void dp_combine_kernel(float* __restrict__ out) {
    const int l = threadIdx.x;    /* one warp */
    double s = 0.0;
    for (int i = l; i < NUNITS; i += 32) s += g_pair_partial[i];
    #pragma unroll
    for (int o = 16; o; o >>= 1) s += __shfl_down_sync(0xffffffffu, s, o);
    if (l == 0) {
        double punish = s / NPAIRS_D;
        double var = (g_sumsq_d - g_sum_d * g_sum_d / (double)NTOT)
                     / (double)(NTOT - 1);
        double sd = sqrt(var);
        float q1 = 0.25f * g_qv[0] + 0.75f * g_qv[1];
        float q3 = 0.75f * g_qv[2] + 0.25f * g_qv[3];
        double dstd = sd - RAND_STD;
        double diqr = (double)(q3 - q1) - IQR_RAND;
        out[0] = (float)(punish + dstd * dstd + diqr * diqr);
    }
}

extern "C" void kernel_launch(void* const* d_in, const int* in_sizes, int n_in,
                              void* d_out, int out_size) {
    (void)in_sizes; (void)n_in; (void)out_size;
    const float* g = (const float*)d_in[0];
    float* out = (float*)d_out;
    dp_main_kernel<<<GRID, TPB, SMEM_BYTES>>>(g);
    dp_combine_kernel<<<1, 32>>>(out);
}

// round 15
// speedup vs baseline: 1.0779x; 1.0779x over previous
#include <cuda_runtime.h>
#include <math_constants.h>
#include <stdint.h>

#define NTOT   18432
#define TPB    512
#define STRIP  512
#define NSTRIP 12
#define NUNITS 144              /* 132 offdiag halves + 12 diag */
#define GRID   147              /* 2 quantile + 1 std + 144 pairwise */
#define NWARPS 16
#define GMAX   1024
#define SELMAX 48
#define NV4    4608             /* NTOT / 4 */
#define SMEM_BYTES 16512

static const double NPAIRS_D = 18871296.0;
static const double RAND_STD = 1.75;
static const double IQR_RAND = 2.45;

__device__ double   g_pair_partial[NUNITS];
__device__ double   g_sum_d, g_sumsq_d;
__device__ float    g_qv[4];

typedef unsigned long long u64;
__device__ __forceinline__ float sqrt_approx(float x) {
    float r; asm("sqrt.approx.f32 %0, %1;" : "=f"(r) : "f"(x)); return r;
}
__device__ __forceinline__ u64 addx2(u64 a, u64 b) {
    u64 r; asm("add.rn.f32x2 %0, %1, %2;" : "=l"(r) : "l"(a), "l"(b)); return r;
}
__device__ __forceinline__ u64 fmax2(u64 a, u64 b, u64 c) {
    u64 r; asm("fma.rn.f32x2 %0, %1, %2, %3;" : "=l"(r) : "l"(a), "l"(b), "l"(c)); return r;
}
__device__ __forceinline__ u64 pack2(float lo, float hi) {
    u64 r; asm("mov.b64 %0, {%1, %2};" : "=l"(r) : "f"(lo), "f"(hi)); return r;
}
__device__ __forceinline__ void unpack2(u64 v, float& lo, float& hi) {
    asm("mov.b64 {%0, %1}, %2;" : "=f"(lo), "=f"(hi) : "l"(v));
}
__device__ __forceinline__ unsigned fkey(float f) {
    unsigned u = __float_as_uint(f);
    return (u & 0x80000000u) ? ~u : (u | 0x80000000u);
}
__device__ __forceinline__ float funkey(unsigned u) {
    unsigned bits = (u & 0x80000000u) ? (u & 0x7fffffffu) : ~u;
    return __uint_as_float(bits);
}
__device__ __forceinline__ void hit(float s, float& acc) {
    if (s < 0.64f) acc += 0.8f - sqrt_approx(fmaxf(s, 0.0f));
}

/* packed broadcast pair loop: PA[m]={x0,x1,y0,y1}, PZ[m]={z0,z1,r0,r1} */
__device__ __forceinline__ void pair_loop(const float4* __restrict__ PA,
                                          const float4* __restrict__ PZ,
                                          int m0, int cnt,
                                          u64 R2, u64 A2, u64 B2, u64 C2,
                                          float& acc) {
    #pragma unroll 2
    for (int q = 0; q < cnt; q += 2) {
        float4 v0 = PA[m0 + q],     z0 = PZ[m0 + q];
        float4 v1 = PA[m0 + q + 1], z1 = PZ[m0 + q + 1];
        u64 sa = addx2(R2, pack2(z0.z, z0.w));
        sa = fmax2(pack2(v0.x, v0.y), A2, sa);
        sa = fmax2(pack2(v0.z, v0.w), B2, sa);
        sa = fmax2(pack2(z0.x, z0.y), C2, sa);
        u64 sb = addx2(R2, pack2(z1.z, z1.w));
        sb = fmax2(pack2(v1.x, v1.y), A2, sb);
        sb = fmax2(pack2(v1.z, v1.w), B2, sb);
        sb = fmax2(pack2(z1.x, z1.y), C2, sb);
        float a0, a1, b0, b1;
        unpack2(sa, a0, a1); unpack2(sb, b0, b1);
        float mn = fminf(fminf(a0, a1), fminf(b0, b1));
        if (mn < 0.64f) { hit(a0, acc); hit(a1, acc); hit(b0, acc); hit(b1, acc); }
    }
}

__global__ void __launch_bounds__(TPB)
dp_main_kernel(const float* __restrict__ g) {
    extern __shared__ unsigned char smem_raw[];
    const int bid = blockIdx.x;
    const int t   = threadIdx.x;
    const int w   = t >> 5;
    const int ln  = t & 31;

    __shared__ unsigned s_wcnt[NWARPS], s_wcnt2[NWARPS];
    __shared__ unsigned s_totA, s_totB, s_tot, s_gcnt, s_gcnt2;
    __shared__ float    s_fred[NWARPS];
    __shared__ float    s_q[2];

    if (bid >= 3 && bid < 3 + 132) {
        /* ===== off-diag half: i-strip a (512) x j-window 256 of strip b ===== */
        const int ob = bid - 3;
        const int tile = ob >> 1, h = ob & 1;
        int a = 0, rem = tile;
        while (rem >= NSTRIP - 1 - a) { rem -= NSTRIP - 1 - a; ++a; }
        const int b = a + 1 + rem;

        float4* PA = (float4*)smem_raw;         /* 128 pair-float4s */
        float4* PZ = PA + 128;
        if (t < 256) {
            const int j = b * STRIP + h * 256 + t;
            float xj = g[3 * j + 0], yj = g[3 * j + 1], zj = g[3 * j + 2];
            float rj = fmaf(zj, zj, fmaf(yj, yj, xj * xj));
            const int m = t >> 1, c = t & 1;
            ((float*)&PA[m])[c]     = xj;
            ((float*)&PA[m])[2 + c] = yj;
            ((float*)&PZ[m])[c]     = zj;
            ((float*)&PZ[m])[2 + c] = rj;
        }
        float xi, yi, zi;
        {
            const int i = a * STRIP + t;
            xi = g[3 * i + 0]; yi = g[3 * i + 1]; zi = g[3 * i + 2];
        }
        __syncthreads();

        const float Ri = fmaf(zi, zi, fmaf(yi, yi, xi * xi));
        const u64 R2 = pack2(Ri, Ri);
        const u64 A2 = pack2(-2.0f * xi, -2.0f * xi);
        const u64 B2 = pack2(-2.0f * yi, -2.0f * yi);
        const u64 C2 = pack2(-2.0f * zi, -2.0f * zi);

        float acc = 0.f;
        pair_loop(PA, PZ, 0, 128, R2, A2, B2, C2, acc);

        #pragma unroll
        for (int o = 16; o; o >>= 1)
            acc += __shfl_down_sync(0xffffffffu, acc, o);
        if (ln == 0) s_fred[w] = acc;
        __syncthreads();
        if (t == 0) {
            float r = 0.f;
            #pragma unroll
            for (int i2 = 0; i2 < NWARPS; ++i2) r += s_fred[i2];
            g_pair_partial[ob] = (double)r;
        }

    } else if (bid >= 3 + 132) {
        /* ===== diag strip: recursive half-split squares + shfl tri(16) ===== */
        const int db = bid - (3 + 132);           /* 0..11 */
        float4* F4 = (float4*)smem_raw;           /* 512 atoms */
        float4* PA = F4 + 512;                    /* 256 pair-float4s */
        float4* PZ = PA + 256;
        {
            const int j = db * STRIP + t;
            float xj = g[3 * j + 0], yj = g[3 * j + 1], zj = g[3 * j + 2];
            float rj = fmaf(zj, zj, fmaf(yj, yj, xj * xj));
            F4[t] = make_float4(xj, yj, zj, rj);
            const int m = t >> 1, c = t & 1;
            ((float*)&PA[m])[c]     = xj;
            ((float*)&PA[m])[2 + c] = yj;
            ((float*)&PZ[m])[c]     = zj;
            ((float*)&PZ[m])[2 + c] = rj;
        }
        __syncthreads();

        float acc = 0.f;
        #pragma unroll
        for (int L = 0; L < 5; ++L) {
            const int halfsz = 256 >> L;
            const int sqid = t >> (9 - L);
            const int r    = t & ((512 >> L) - 1);
            const int il   = sqid * (512 >> L) + (r & (halfsz - 1));
            const int jh   = r >> (8 - L);
            const int j0   = sqid * (512 >> L) + halfsz + jh * (halfsz >> 1);
            float4 mi = F4[il];
            const u64 R2 = pack2(mi.w, mi.w);
            const u64 A2 = pack2(-2.0f * mi.x, -2.0f * mi.x);
            const u64 B2 = pack2(-2.0f * mi.y, -2.0f * mi.y);
            const u64 C2 = pack2(-2.0f * mi.z, -2.0f * mi.z);
            pair_loop(PA, PZ, j0 >> 1, 64 >> L, R2, A2, B2, C2, acc);
        }
        /* tri(16) groups via shuffle */
        {
            float4 me = F4[t];
            const float mx = -2.0f * me.x, my = -2.0f * me.y, mz = -2.0f * me.z;
            const int hl = t & 15;
            #pragma unroll
            for (int d = 1; d <= 8; ++d) {
                int src = (hl + d) & 15;
                float xo = __shfl_sync(0xffffffffu, me.x, src, 16);
                float yo = __shfl_sync(0xffffffffu, me.y, src, 16);
                float zo = __shfl_sync(0xffffffffu, me.z, src, 16);
                float ro = __shfl_sync(0xffffffffu, me.w, src, 16);
                if (d < 8 || hl < 8) {
                    float s = fmaf(mz, zo, fmaf(my, yo, fmaf(mx, xo, me.w + ro)));
                    hit(s, acc);
                }
            }
        }

        #pragma unroll
        for (int o = 16; o; o >>= 1)
            acc += __shfl_down_sync(0xffffffffu, acc, o);
        if (ln == 0) s_fred[w] = acc;
        __syncthreads();
        if (t == 0) {
            float r = 0.f;
            #pragma unroll
            for (int i2 = 0; i2 < NWARPS; ++i2) r += s_fred[i2];
            g_pair_partial[132 + db] = (double)r;
        }

    } else if (bid < 2) {
        /* ===== exact quantile pair (ranks k0, k0+1): fused fast bracket ===== */
        const int qb = bid;
        const unsigned k0 = qb ? 13823u : 4607u;
        const float gA = qb ? 0.6245f : -0.7245f;
        const float gB = qb ? 0.7245f : -0.6245f;
        const float4* gv4 = (const float4*)g;
        float* sub  = (float*)smem_raw;
        float* sub2 = sub + GMAX;

        float lo, hi; unsigned cL, cH;
        bool allEq = false;

        if (t == 0) s_gcnt = 0;
        __syncthreads();

        {
            unsigned cA = 0, cB = 0;
            for (int e = t; e < NV4; e += TPB) {
                float4 q = gv4[e];
                float qq[4] = {q.x, q.y, q.z, q.w};
                #pragma unroll
                for (int c4 = 0; c4 < 4; ++c4) {
                    float x = qq[c4];
                    cA += (x < gA) ? 1u : 0u;
                    cB += (x < gB) ? 1u : 0u;
                    if (x >= gA && x < gB) {
                        unsigned p = atomicAdd(&s_gcnt, 1u);
                        if (p < (unsigned)GMAX) sub[p] = x;
                    }
                }
            }
            #pragma unroll
            for (int o = 16; o; o >>= 1) {
                cA += __shfl_down_sync(0xffffffffu, cA, o);
                cB += __shfl_down_sync(0xffffffffu, cB, o);
            }
            if (ln == 0) { s_wcnt[w] = cA; s_wcnt2[w] = cB; }
            __syncthreads();
            if (t == 0) {
                unsigned ta = 0, tb = 0;
                #pragma unroll
                for (int i2 = 0; i2 < NWARPS; ++i2) { ta += s_wcnt[i2]; tb += s_wcnt2[i2]; }
                s_totA = ta; s_totB = tb;
            }
            __syncthreads();
        }

        const bool fast = (s_totA <= k0) && (k0 < s_totB) &&
                          (s_totB - s_totA <= (unsigned)GMAX);
        if (fast) {
            lo = gA; hi = gB; cL = s_totA; cH = s_totB;
        } else {
            lo = -CUDART_INF_F; hi = CUDART_INF_F; cL = 0; cH = NTOT;
            for (int it = 0; it < 48; ++it) {
                if (cH - cL <= (unsigned)GMAX) break;
                const unsigned klo = fkey(lo), khi = fkey(hi);
                if (khi - klo <= 1u) { allEq = true; break; }
                float cand;
                if (it < 8) {
                    double frac = ((double)k0 + 0.5 - (double)cL) / (double)(cH - cL);
                    if (lo == -CUDART_INF_F || hi == CUDART_INF_F)
                        cand = funkey(klo + (khi - klo) / 2u);
                    else
                        cand = (float)((double)lo + frac * ((double)hi - (double)lo));
                } else cand = funkey(klo + (khi - klo) / 2u);
                {
                    unsigned kc = fkey(cand);
                    if (!(kc > klo && kc < khi)) cand = funkey(klo + (khi - klo) / 2u);
                }
                unsigned c = 0;
                for (int e = t; e < NV4; e += TPB) {
                    float4 q = gv4[e];
                    c += (q.x < cand) ? 1u : 0u;
                    c += (q.y < cand) ? 1u : 0u;
                    c += (q.z < cand) ? 1u : 0u;
                    c += (q.w < cand) ? 1u : 0u;
                }
                #pragma unroll
                for (int o = 16; o; o >>= 1) c += __shfl_down_sync(0xffffffffu, c, o);
                if (ln == 0) s_wcnt[w] = c;
                __syncthreads();
                if (t == 0) {
                    unsigned totc = 0;
                    #pragma unroll
                    for (int i2 = 0; i2 < NWARPS; ++i2) totc += s_wcnt[i2];
                    s_tot = totc;
                }
                __syncthreads();
                const unsigned ctot = s_tot;
                if (ctot <= k0) { lo = cand; cL = ctot; }
                else            { hi = cand; cH = ctot; }
            }
            if (!allEq) {
                __syncthreads();
                if (t == 0) s_gcnt = 0;
                __syncthreads();
                for (int e = t; e < NV4; e += TPB) {
                    float4 q = gv4[e];
                    float qq[4] = {q.x, q.y, q.z, q.w};
                    #pragma unroll
                    for (int c4 = 0; c4 < 4; ++c4) {
                        float x = qq[c4];
                        if (x >= lo && x < hi) {
                            unsigned p = atomicAdd(&s_gcnt, 1u);
                            if (p < (unsigned)GMAX) sub[p] = x;
                        }
                    }
                }
                __syncthreads();
            }
        }

        if (allEq) {
            if (t == 0) { s_q[0] = lo; s_q[1] = lo; }
            __syncthreads();
        } else {
            __syncthreads();
            const unsigned mm0 = s_gcnt;
            const unsigned cL0 = cL;

            unsigned cLg = cL, cHg = cH;
            float lo2 = lo, hi2 = hi;
            for (int it = 0; it < 64; ++it) {
                if (cHg - cLg <= (unsigned)SELMAX) break;
                const unsigned klo = fkey(lo2), khi = fkey(hi2);
                if (khi - klo <= 1u) break;
                float cand;
                if (it < 10) {
                    double frac = ((double)k0 + 0.5 - (double)cLg) / (double)(cHg - cLg);
                    cand = (float)((double)lo2 + frac * ((double)hi2 - (double)lo2));
                } else cand = funkey(klo + (khi - klo) / 2u);
                {
                    unsigned kc = fkey(cand);
                    if (!(kc > klo && kc < khi)) cand = funkey(klo + (khi - klo) / 2u);
                }
                unsigned c = 0;
                for (unsigned i2 = t; i2 < mm0; i2 += TPB)
                    c += (sub[i2] < cand) ? 1u : 0u;
                #pragma unroll
                for (int o = 16; o; o >>= 1) c += __shfl_down_sync(0xffffffffu, c, o);
                if (ln == 0) s_wcnt[w] = c;
                __syncthreads();
                if (t == 0) {
                    unsigned totc = 0;
                    #pragma unroll
                    for (int i2 = 0; i2 < NWARPS; ++i2) totc += s_wcnt[i2];
                    s_tot = totc;
                }
                __syncthreads();
                const unsigned cg = cL0 + s_tot;
                if (cg <= k0) { lo2 = cand; cLg = cg; }
                else          { hi2 = cand; cHg = cg; }
            }

            if (t == 0) s_gcnt2 = 0;
            __syncthreads();
            for (unsigned i2 = t; i2 < mm0; i2 += TPB) {
                float x = sub[i2];
                if (x >= lo2 && x < hi2) {
                    unsigned p = atomicAdd(&s_gcnt2, 1u);
                    if (p < 64u) sub2[p] = x;
                }
            }
            __syncthreads();
            const unsigned mm2 = s_gcnt2;
            if (mm2 <= 64u) {
                if (t < (int)mm2) {
                    float x = sub2[t];
                    unsigned cl = 0, ce = 0;
                    for (unsigned jj = 0; jj < mm2; ++jj) {
                        float y = sub2[jj];
                        cl += (y < x) ? 1u : 0u;
                        ce += (y == x) ? 1u : 0u;
                    }
                    const unsigned glo = cLg + cl;
                    if (glo <= k0 && k0 < glo + ce)           s_q[0] = x;
                    if (glo <= k0 + 1u && k0 + 1u < glo + ce) s_q[1] = x;
                }
            } else {
                for (unsigned i2 = t; i2 < mm0; i2 += TPB) {
                    float x = sub[i2];
                    if (x >= lo2 && x < hi2) {
                        unsigned cl = 0, ce = 0;
                        for (unsigned jj = 0; jj < mm0; ++jj) {
                            float y = sub[jj];
                            cl += (y < x) ? 1u : 0u;
                            ce += (y == x) ? 1u : 0u;
                        }
                        const unsigned glo = cL0 + cl;
                        if (glo <= k0 && k0 < glo + ce)           s_q[0] = x;
                        if (glo <= k0 + 1u && k0 + 1u < glo + ce) s_q[1] = x;
                    }
                }
            }
            if (k0 + 1u >= cHg) {
                float mn = CUDART_INF_F;
                for (int e = t; e < NV4; e += TPB) {
                    float4 q = gv4[e];
                    if (q.x >= hi2) mn = fminf(mn, q.x);
                    if (q.y >= hi2) mn = fminf(mn, q.y);
                    if (q.z >= hi2) mn = fminf(mn, q.z);
                    if (q.w >= hi2) mn = fminf(mn, q.w);
                }
                #pragma unroll
                for (int o = 16; o; o >>= 1)
                    mn = fminf(mn, __shfl_down_sync(0xffffffffu, mn, o));
                if (ln == 0) s_fred[w] = mn;
                __syncthreads();
                if (t == 0) {
                    float r = s_fred[0];
                    #pragma unroll
                    for (int i2 = 1; i2 < NWARPS; ++i2) r = fminf(r, s_fred[i2]);
                    s_q[1] = r;
                }
            }
            __syncthreads();
        }
        if (t == 0) {
            g_qv[2 * qb + 0] = s_q[0];
            g_qv[2 * qb + 1] = s_q[1];
        }

    } else {
        /* ============ std sums (fp64, deterministic) ============ */
        __shared__ double sds[NWARPS], sdq[NWARPS];
        const float4* gv4 = (const float4*)g;
        double s = 0.0, s2 = 0.0;
        for (int e = t; e < NV4; e += TPB) {
            float4 q = gv4[e];
            double x0 = (double)q.x, x1 = (double)q.y;
            double x2 = (double)q.z, x3 = (double)q.w;
            s  += (x0 + x1) + (x2 + x3);
            s2 += (x0 * x0 + x1 * x1) + (x2 * x2 + x3 * x3);
        }
        #pragma unroll
        for (int o = 16; o; o >>= 1) {
            s  += __shfl_down_sync(0xffffffffu, s,  o);
            s2 += __shfl_down_sync(0xffffffffu, s2, o);
        }
        if (ln == 0) { sds[w] = s; sdq[w] = s2; }
        __syncthreads();
        if (t == 0) {
            double aa = 0.0, bb = 0.0;
            #pragma unroll
            for (int i2 = 0; i2 < NWARPS; ++i2) { aa += sds[i2]; bb += sdq[i2]; }
            g_sum_d = aa; g_sumsq_d = bb;
        }
    }
}

/* combine: 160 threads. Threads 0-143 load one partial each (parallel, one
   L2 round). Warp 0 then reduces from smem in the SAME index order as the
   old serial-gmem loop (lane l sums l, l+32, ... ascending) — bit-identical. */
__global__ void __launch_bounds__(160)
dp_combine_kernel(float* __restrict__ out) {
    __shared__ double sp[NUNITS];
    const int t = threadIdx.x;
    if (t < NUNITS) sp[t] = g_pair_partial[t];
    __syncthreads();
    if (t < 32) {
        double s = 0.0;
        #pragma unroll
        for (int i = t; i < NUNITS; i += 32) s += sp[i];
        #pragma unroll
        for (int o = 16; o; o >>= 1) s += __shfl_down_sync(0xffffffffu, s, o);
        if (t == 0) {
            double punish = s / NPAIRS_D;
            double var = (g_sumsq_d - g_sum_d * g_sum_d / (double)NTOT)
                         / (double)(NTOT - 1);
            double sd = sqrt(var);
            float q1 = 0.25f * g_qv[0] + 0.75f * g_qv[1];
            float q3 = 0.75f * g_qv[2] + 0.25f * g_qv[3];
            double dstd = sd - RAND_STD;
            double diqr = (double)(q3 - q1) - IQR_RAND;
            out[0] = (float)(punish + dstd * dstd + diqr * diqr);
        }
    }
}

extern "C" void kernel_launch(void* const* d_in, const int* in_sizes, int n_in,
                              void* d_out, int out_size) {
    (void)in_sizes; (void)n_in; (void)out_size;
    const float* g = (const float*)d_in[0];
    float* out = (float*)d_out;
    dp_main_kernel<<<GRID, TPB, SMEM_BYTES>>>(g);
    dp_combine_kernel<<<1, 160>>>(out);
}